// round 4
// baseline (speedup 1.0000x reference)
#include <cuda_runtime.h>

#define BATCH 1024
#define NPTS  128
#define MPTS  128
#define TIME  10

// Scratch (no allocation allowed) + cross-block completion counter
__device__ float g_part1[BATCH];
__device__ float g_part2[BATCH];
__device__ float g_part3[BATCH];
__device__ unsigned int g_count = 0;

__global__ __launch_bounds__(256, 6)
void dmloss_fused(const float* __restrict__ ini_pred,   // [B,N,2]
                  const float* __restrict__ pred_polys, // [B,N,2]
                  const float* __restrict__ gt_polys,   // [B,M,2]
                  const float* __restrict__ kmask,      // [B,M]
                  float* __restrict__ out)
{
    __shared__ float4 s_seg[MPTS];     // ax, ay, ex, ey  (a = prev vertex, e = cur - prev)
    __shared__ float2 s_cg[MPTS];      // c = -10/e2,  g = e2/100
    __shared__ float2 s_gt[MPTS];      // current vertex b
    __shared__ float4 s_pp[NPTS];      // px, py, 0.5*(px^2+py^2), 0   (ini_pred)
    __shared__ float  s_step[TIME];    // exact k/10 (epilogue only)
    __shared__ float  s_xd1[256], s_xa1[256];   // loop1 exchange
    __shared__ float  s_xd2[256];               // loop2 exchange
    __shared__ int    s_xi2[256];
    __shared__ float  s_r1[8], s_r2[8], s_r3[8];
    __shared__ int    s_last;

    const int tid  = threadIdx.x;
    const int t    = tid & 127;
    const int half = tid >> 7;      // 0: lower ranges, 1: upper ranges
    const int b    = blockIdx.x;

    // ---- setup: lower half builds segment data, upper half builds pred data ----
    if (half == 0) {
        const float2* gt = (const float2*)(gt_polys + (size_t)b * MPTS * 2);
        const float2 bcur  = gt[t];
        const float2 aprev = gt[(t + MPTS - 1) & (MPTS - 1)];
        const float ex = bcur.x - aprev.x;
        const float ey = bcur.y - aprev.y;
        const float e2 = ex * ex + ey * ey;
        s_seg[t] = make_float4(aprev.x, aprev.y, ex, ey);
        s_cg[t]  = make_float2(-10.0f / fmaxf(e2, 1e-30f), e2 * 0.01f);
        s_gt[t]  = bcur;
        if (t < TIME) s_step[t] = (float)t / 10.0f;
    } else {
        const float2* ip = (const float2*)(ini_pred + (size_t)b * NPTS * 2);
        const float2 p = ip[t];
        s_pp[t] = make_float4(p.x, p.y, 0.5f * fmaf(p.x, p.x, p.y * p.y), 0.0f);
    }
    __syncthreads();

    // ---- loop1: pred t -> nearest interp-gt over segments [64*half, 64*half+64) ----
    const float4 pq = s_pp[t];
    const float px = pq.x, py = pq.y;
    float bestd   = 3.402823466e38f;
    float bestaux = 0.0f;
    {
        const int m0 = half << 6;
        float mf = (float)(m0 * 10);
        #pragma unroll 4
        for (int mm = 0; mm < 64; mm++) {
            const int m = m0 + mm;
            const float4 sg = s_seg[m];
            const float2 cg = s_cg[m];
            const float wx = sg.x - px;
            const float wy = sg.y - py;
            const float wd = fmaf(wy, sg.w, wx * sg.z);      // w . e
            const float w2 = fmaf(wy, wy, wx * wx);          // |w|^2
            const float kf = wd * cg.x;                      // continuous minimizer in k units
            const float dp = fmaf(wd * 0.1f, kf, w2);        // dperp = w2 - wd^2/e2
            const float kc = fminf(fmaxf(kf, 0.0f), 9.0f);
            const float kr = rintf(kc);                      // sampled minimizer
            const float dl = kr - kf;
            const float d  = fmaf(cg.y * dl, dl, dp);        // e2/100*(k-kf)^2 + dperp
            const float aux = mf + kr;                       // 10*m + k, exact in fp32
            if (d < bestd) { bestd = d; bestaux = aux; }
            mf += 10.0f;
        }
    }

    // ---- loop2: gt t -> nearest pred over preds [64*half, 64*half+64) ----
    const float2 gv = s_gt[t];
    float bscore = 3.402823466e38f;
    int   bi2 = 0;
    {
        const int n0 = half << 6;
        #pragma unroll 4
        for (int nn = 0; nn < 64; nn++) {
            const int n = n0 + nn;
            const float4 q = s_pp[n];
            const float s = fmaf(-gv.x, q.x, fmaf(-gv.y, q.y, q.z));  // 0.5|q|^2 - g.q
            if (s < bscore) { bscore = s; bi2 = n; }
        }
    }

    // ---- exchange halves & merge (lower index wins exact ties -> strict <) ----
    s_xd1[tid] = bestd; s_xa1[tid] = bestaux;
    s_xd2[tid] = bscore; s_xi2[tid] = bi2;
    __syncthreads();

    float c1 = 0.0f, c2 = 0.0f, c3 = 0.0f;
    if (half == 0) {
        const float d1 = s_xd1[tid + 128];
        if (d1 < bestd) { bestd = d1; bestaux = s_xa1[tid + 128]; }
        const float d2 = s_xd2[tid + 128];
        if (d2 < bscore) { bscore = d2; bi2 = s_xi2[tid + 128]; }

        // loss_pred2gt contribution: reference interp form b*t + a*(1-t)
        const int   besti = (int)bestaux;
        const int   mseg  = besti / 10;
        const int   k     = besti - mseg * 10;
        const float tk = s_step[k];
        const float rt = 1.0f - tk;
        const float4 sg = s_seg[mseg];
        const float2 bb = s_gt[mseg];
        const float qx = bb.x * tk + sg.x * rt;
        const float qy = bb.y * tk + sg.y * rt;
        const float2* pp = (const float2*)(pred_polys + (size_t)b * NPTS * 2);
        const float2 pv = pp[t];
        c1 = fabsf(pv.x - qx) + fabsf(pv.y - qy);

        // loss_gt2pred contribution
        const float2 nearp = pp[bi2];
        const float  mk = kmask[(size_t)b * MPTS + t];
        c2 = (fabsf(nearp.x - gv.x) + fabsf(nearp.y - gv.y)) * mk;
        c3 = 2.0f * mk;
    }

    // ---- reduction: warp shuffles, then 8 warp partials ----
    #pragma unroll
    for (int o = 16; o > 0; o >>= 1) {
        c1 += __shfl_down_sync(0xFFFFFFFFu, c1, o);
        c2 += __shfl_down_sync(0xFFFFFFFFu, c2, o);
        c3 += __shfl_down_sync(0xFFFFFFFFu, c3, o);
    }
    const int w = tid >> 5;
    if ((tid & 31) == 0) { s_r1[w] = c1; s_r2[w] = c2; s_r3[w] = c3; }
    __syncthreads();
    if (tid == 0) {
        float a = 0.0f, bs = 0.0f, cc = 0.0f;
        #pragma unroll
        for (int i = 0; i < 8; i++) { a += s_r1[i]; bs += s_r2[i]; cc += s_r3[i]; }
        g_part1[b] = a; g_part2[b] = bs; g_part3[b] = cc;
        __threadfence();
        const unsigned old = atomicAdd(&g_count, 1u);
        s_last = (old == (unsigned)(BATCH - 1)) ? 1 : 0;
    }
    __syncthreads();

    // ---- last block: deterministic final reduction ----
    if (s_last) {
        float a = 0.0f, bs = 0.0f, cc = 0.0f;
        #pragma unroll
        for (int i = tid; i < BATCH; i += 256) {
            a  += g_part1[i];
            bs += g_part2[i];
            cc += g_part3[i];
        }
        #pragma unroll
        for (int o = 16; o > 0; o >>= 1) {
            a  += __shfl_down_sync(0xFFFFFFFFu, a, o);
            bs += __shfl_down_sync(0xFFFFFFFFu, bs, o);
            cc += __shfl_down_sync(0xFFFFFFFFu, cc, o);
        }
        if ((tid & 31) == 0) { s_r1[w] = a; s_r2[w] = bs; s_r3[w] = cc; }
        __syncthreads();
        if (tid == 0) {
            float fa = 0.0f, fb = 0.0f, fc = 0.0f;
            #pragma unroll
            for (int i = 0; i < 8; i++) { fa += s_r1[i]; fb += s_r2[i]; fc += s_r3[i]; }
            const float loss_pred2gt = fa / (float)(BATCH * NPTS * 2);
            const float loss_gt2pred = fb / (fc + 1.0f);
            out[0] = (loss_gt2pred + loss_pred2gt) * 0.5f;
            g_count = 0;   // reset for next graph replay
        }
    }
}

extern "C" void kernel_launch(void* const* d_in, const int* in_sizes, int n_in,
                              void* d_out, int out_size)
{
    const float* ini_pred   = (const float*)d_in[0];
    const float* pred_polys = (const float*)d_in[1];
    const float* gt_polys   = (const float*)d_in[2];
    const float* kmask      = (const float*)d_in[3];
    float* out = (float*)d_out;

    dmloss_fused<<<BATCH, 256>>>(ini_pred, pred_polys, gt_polys, kmask, out);
}

// round 5
// speedup vs baseline: 1.5431x; 1.5431x over previous
#include <cuda_runtime.h>

#define BATCH 1024
#define NPTS  128
#define MPTS  128
#define TIME  10

// Scratch (no allocation allowed) + cross-block completion counter
__device__ float g_part1[BATCH];
__device__ float g_part2[BATCH];
__device__ float g_part3[BATCH];
__device__ unsigned int g_count = 0;

__global__ __launch_bounds__(128, 8)
void dmloss_fused(const float* __restrict__ ini_pred,   // [B,N,2]
                  const float* __restrict__ pred_polys, // [B,N,2]
                  const float* __restrict__ gt_polys,   // [B,M,2]
                  const float* __restrict__ kmask,      // [B,M]
                  float* __restrict__ out)
{
    __shared__ float4 s_seg[MPTS];    // ax, ay, ex, ey  (a = prev vertex, e = cur - prev)
    __shared__ float2 s_cge[MPTS];    // c = -10/e2,  e2c = 0.01*e2
    __shared__ float2 s_gt[MPTS];     // current vertex b
    __shared__ float4 s_pp[NPTS];     // px, py, 0.5*|p|^2, 0   (ini_pred)
    __shared__ float  s_step[TIME];   // exact k/10 (epilogue only)
    __shared__ float  s_r1[4], s_r2[4], s_r3[4];
    __shared__ int    s_last;

    const int tid = threadIdx.x;
    const int b   = blockIdx.x;

    // ---- setup (each thread: one segment + one pred point) ----
    const float2* gt = (const float2*)(gt_polys + (size_t)b * MPTS * 2);
    const float2 bcur  = gt[tid];
    const float2 aprev = gt[(tid + MPTS - 1) & (MPTS - 1)];
    {
        const float ex = bcur.x - aprev.x;
        const float ey = bcur.y - aprev.y;
        const float e2 = ex * ex + ey * ey;
        s_seg[tid] = make_float4(aprev.x, aprev.y, ex, ey);
        s_cge[tid] = make_float2(-10.0f / fmaxf(e2, 1e-30f), 0.01f * e2);
        s_gt[tid]  = bcur;
    }
    const float2* ip = (const float2*)(ini_pred + (size_t)b * NPTS * 2);
    const float2 p = ip[tid];
    s_pp[tid] = make_float4(p.x, p.y, 0.5f * fmaf(p.x, p.x, p.y * p.y), 0.0f);
    if (tid < TIME) s_step[tid] = (float)tid / 10.0f;
    __syncthreads();

    const float px = p.x, py = p.y;
    const float gx = bcur.x, gy = bcur.y;

    // ---- fused scan: loop1 (pred->interp-gt) + loop2 (gt->pred), dual chains ----
    float bd0 = 3.402823466e38f, bd1 = 3.402823466e38f;
    float ba0 = 0.0f,            ba1 = 0.0f;
    float bs0 = 3.402823466e38f, bs1 = 3.402823466e38f;
    int   bi0 = 0,               bi1 = 0;

    #pragma unroll 4
    for (int i = 0; i < 64; i++) {
        // --- segment chain A: m = i ---
        {
            const float4 sg = s_seg[i];
            const float2 cg = s_cge[i];
            const float wx = sg.x - px;
            const float wy = sg.y - py;
            const float wd = fmaf(wy, sg.w, wx * sg.z);
            const float w2 = fmaf(wy, wy, wx * wx);
            const float kf = wd * cg.x;
            const float kr = rintf(fminf(fmaxf(kf, 0.0f), 9.0f));
            const float d  = fmaf(kr, fmaf(kr, cg.y, 0.2f * wd), w2);
            const float aux = (float)(10 * i) + kr;
            if (d < bd0) { bd0 = d; ba0 = aux; }
        }
        // --- segment chain B: m = i + 64 ---
        {
            const float4 sg = s_seg[i + 64];
            const float2 cg = s_cge[i + 64];
            const float wx = sg.x - px;
            const float wy = sg.y - py;
            const float wd = fmaf(wy, sg.w, wx * sg.z);
            const float w2 = fmaf(wy, wy, wx * wx);
            const float kf = wd * cg.x;
            const float kr = rintf(fminf(fmaxf(kf, 0.0f), 9.0f));
            const float d  = fmaf(kr, fmaf(kr, cg.y, 0.2f * wd), w2);
            const float aux = (float)(10 * (i + 64)) + kr;
            if (d < bd1) { bd1 = d; ba1 = aux; }
        }
        // --- pred chain A: n = i ---
        {
            const float4 q = s_pp[i];
            const float s = fmaf(-gx, q.x, fmaf(-gy, q.y, q.z));  // 0.5|q|^2 - g.q
            if (s < bs0) { bs0 = s; bi0 = i; }
        }
        // --- pred chain B: n = i + 64 ---
        {
            const float4 q = s_pp[i + 64];
            const float s = fmaf(-gx, q.x, fmaf(-gy, q.y, q.z));
            if (s < bs1) { bs1 = s; bi1 = i + 64; }
        }
    }
    // merge chains: lower-range chain wins exact ties (strict <)
    if (bd1 < bd0) { bd0 = bd1; ba0 = ba1; }
    if (bs1 < bs0) { bs0 = bs1; bi0 = bi1; }

    // ---- epilogue: reference-form interpolation at winner ----
    const float2* pp = (const float2*)(pred_polys + (size_t)b * NPTS * 2);
    float c1, c2, c3;
    {
        const int besti = (int)ba0;
        const int mseg  = besti / 10;
        const int k     = besti - mseg * 10;
        const float tk = s_step[k];
        const float rt = 1.0f - tk;
        const float4 sg = s_seg[mseg];
        const float2 bb = s_gt[mseg];
        const float qx = bb.x * tk + sg.x * rt;
        const float qy = bb.y * tk + sg.y * rt;
        const float2 pv = pp[tid];
        c1 = fabsf(pv.x - qx) + fabsf(pv.y - qy);

        const float2 nearp = pp[bi0];
        const float  mk = kmask[(size_t)b * MPTS + tid];
        c2 = (fabsf(nearp.x - gx) + fabsf(nearp.y - gy)) * mk;
        c3 = 2.0f * mk;
    }

    // ---- reduction: warp shuffles, 4 warp partials ----
    #pragma unroll
    for (int o = 16; o > 0; o >>= 1) {
        c1 += __shfl_down_sync(0xFFFFFFFFu, c1, o);
        c2 += __shfl_down_sync(0xFFFFFFFFu, c2, o);
        c3 += __shfl_down_sync(0xFFFFFFFFu, c3, o);
    }
    const int w = tid >> 5;
    if ((tid & 31) == 0) { s_r1[w] = c1; s_r2[w] = c2; s_r3[w] = c3; }
    __syncthreads();
    if (tid == 0) {
        float a = 0.0f, bsum = 0.0f, cc = 0.0f;
        #pragma unroll
        for (int i = 0; i < 4; i++) { a += s_r1[i]; bsum += s_r2[i]; cc += s_r3[i]; }
        g_part1[b] = a; g_part2[b] = bsum; g_part3[b] = cc;
        __threadfence();
        const unsigned old = atomicAdd(&g_count, 1u);
        s_last = (old == (unsigned)(BATCH - 1)) ? 1 : 0;
    }
    __syncthreads();

    // ---- last block: deterministic final reduction ----
    if (s_last) {
        float a = 0.0f, bsum = 0.0f, cc = 0.0f;
        #pragma unroll
        for (int i = tid; i < BATCH; i += 128) {
            a    += g_part1[i];
            bsum += g_part2[i];
            cc   += g_part3[i];
        }
        #pragma unroll
        for (int o = 16; o > 0; o >>= 1) {
            a    += __shfl_down_sync(0xFFFFFFFFu, a, o);
            bsum += __shfl_down_sync(0xFFFFFFFFu, bsum, o);
            cc   += __shfl_down_sync(0xFFFFFFFFu, cc, o);
        }
        if ((tid & 31) == 0) { s_r1[w] = a; s_r2[w] = bsum; s_r3[w] = cc; }
        __syncthreads();
        if (tid == 0) {
            float fa = 0.0f, fb = 0.0f, fc = 0.0f;
            #pragma unroll
            for (int i = 0; i < 4; i++) { fa += s_r1[i]; fb += s_r2[i]; fc += s_r3[i]; }
            const float loss_pred2gt = fa / (float)(BATCH * NPTS * 2);
            const float loss_gt2pred = fb / (fc + 1.0f);
            out[0] = (loss_gt2pred + loss_pred2gt) * 0.5f;
            g_count = 0;   // reset for next graph replay
        }
    }
}

extern "C" void kernel_launch(void* const* d_in, const int* in_sizes, int n_in,
                              void* d_out, int out_size)
{
    const float* ini_pred   = (const float*)d_in[0];
    const float* pred_polys = (const float*)d_in[1];
    const float* gt_polys   = (const float*)d_in[2];
    const float* kmask      = (const float*)d_in[3];
    float* out = (float*)d_out;

    dmloss_fused<<<BATCH, 128>>>(ini_pred, pred_polys, gt_polys, kmask, out);
}

// round 8
// speedup vs baseline: 1.5452x; 1.0014x over previous
#include <cuda_runtime.h>

#define BATCH 1024
#define NPTS  128
#define MPTS  128
#define TIME  10

// Scratch (no allocation allowed) + cross-block completion counter
__device__ float g_part1[BATCH];
__device__ float g_part2[BATCH];
__device__ float g_part3[BATCH];
__device__ unsigned int g_count = 0;

__global__ __launch_bounds__(128, 7)
void dmloss_fused(const float* __restrict__ ini_pred,   // [B,N,2]
                  const float* __restrict__ pred_polys, // [B,N,2]
                  const float* __restrict__ gt_polys,   // [B,M,2]
                  const float* __restrict__ kmask,      // [B,M]
                  float* __restrict__ out)
{
    __shared__ float4 s_segA[MPTS];   // 0.2ex, 0.2ey, -50/e2, 0.01e2
    __shared__ float4 s_segB[MPTS];   // -2ax, -2ay, |a|^2, a.(0.2e)
    __shared__ float2 s_gt[MPTS];     // current vertex b
    __shared__ float4 s_pp[NPTS];     // px, py, 0.5|p|^2, (float)n
    __shared__ float  s_step[TIME];   // exact k/10 (epilogue only)
    __shared__ float  s_r1[4], s_r2[4], s_r3[4];
    __shared__ int    s_last;

    const int tid = threadIdx.x;
    const int b   = blockIdx.x;

    // ---- setup (each thread: one segment + one pred point) ----
    const float2* gt = (const float2*)(gt_polys + (size_t)b * MPTS * 2);
    const float2 bcur  = gt[tid];
    const float2 aprev = gt[(tid + MPTS - 1) & (MPTS - 1)];
    {
        const float ex  = bcur.x - aprev.x;
        const float ey  = bcur.y - aprev.y;
        const float e2  = ex * ex + ey * ey;
        const float ex5 = 0.2f * ex;
        const float ey5 = 0.2f * ey;
        s_segA[tid] = make_float4(ex5, ey5, -50.0f / fmaxf(e2, 1e-30f), 0.01f * e2);
        s_segB[tid] = make_float4(-2.0f * aprev.x, -2.0f * aprev.y,
                                  fmaf(aprev.x, aprev.x, aprev.y * aprev.y),
                                  fmaf(aprev.x, ex5, aprev.y * ey5));
        s_gt[tid]  = bcur;
    }
    const float2* ip = (const float2*)(ini_pred + (size_t)b * NPTS * 2);
    const float2 p = ip[tid];
    s_pp[tid] = make_float4(p.x, p.y, 0.5f * fmaf(p.x, p.x, p.y * p.y), (float)tid);
    if (tid < TIME) s_step[tid] = (float)tid / 10.0f;
    __syncthreads();

    const float px = p.x, py = p.y;
    const float gx = bcur.x, gy = bcur.y;

    // ---- fused scan: loop1 (pred->interp-gt) + loop2 (gt->pred), dual chains ----
    float bd0 = 3.402823466e38f, bd1 = 3.402823466e38f;
    float ba0 = 0.0f,            ba1 = 0.0f;
    float bs0 = 3.402823466e38f, bs1 = 3.402823466e38f;
    float bi0 = 0.0f,            bi1 = 0.0f;
    float mf0 = 0.0f,            mf1 = 640.0f;   // 10*m base per chain

    #pragma unroll 4
    for (int i = 0; i < 64; i++) {
        // --- segment chain A: m = i ---
        {
            const float4 sa = s_segA[i];
            const float4 sb = s_segB[i];
            const float pe  = fmaf(py, sa.y, px * sa.x);          // p.(0.2e)
            const float wd2 = sb.w - pe;                           // 0.2*(w.e)
            const float kf  = wd2 * sa.z;                          // -10(w.e)/e2
            const float kr  = rintf(fminf(fmaxf(kf, 0.0f), 9.0f));
            const float base  = fmaf(px, sb.x, fmaf(py, sb.y, sb.z)); // |a|^2-2a.p
            const float score = fmaf(kr, fmaf(kr, sa.w, wd2), base);
            if (score < bd0) { bd0 = score; ba0 = mf0 + kr; }
        }
        // --- segment chain B: m = i + 64 ---
        {
            const float4 sa = s_segA[i + 64];
            const float4 sb = s_segB[i + 64];
            const float pe  = fmaf(py, sa.y, px * sa.x);
            const float wd2 = sb.w - pe;
            const float kf  = wd2 * sa.z;
            const float kr  = rintf(fminf(fmaxf(kf, 0.0f), 9.0f));
            const float base  = fmaf(px, sb.x, fmaf(py, sb.y, sb.z));
            const float score = fmaf(kr, fmaf(kr, sa.w, wd2), base);
            if (score < bd1) { bd1 = score; ba1 = mf1 + kr; }
        }
        // --- pred chain A: n = i ---
        {
            const float4 q = s_pp[i];
            const float s = fmaf(-gx, q.x, fmaf(-gy, q.y, q.z));  // 0.5|q|^2 - g.q
            if (s < bs0) { bs0 = s; bi0 = q.w; }
        }
        // --- pred chain B: n = i + 64 ---
        {
            const float4 q = s_pp[i + 64];
            const float s = fmaf(-gx, q.x, fmaf(-gy, q.y, q.z));
            if (s < bs1) { bs1 = s; bi1 = q.w; }
        }
        mf0 += 10.0f; mf1 += 10.0f;
    }
    // merge chains: lower-range chain wins exact ties (strict <)
    if (bd1 < bd0) { bd0 = bd1; ba0 = ba1; }
    if (bs1 < bs0) { bs0 = bs1; bi0 = bi1; }

    // ---- epilogue: reference-form interpolation at winner ----
    const float2* pp = (const float2*)(pred_polys + (size_t)b * NPTS * 2);
    float c1, c2, c3;
    {
        const int besti = (int)ba0;
        const int mseg  = besti / 10;
        const int k     = besti - mseg * 10;
        const float tk = s_step[k];
        const float rt = 1.0f - tk;
        const float4 sb = s_segB[mseg];
        const float ax = -0.5f * sb.x;      // exact recovery of aprev
        const float ay = -0.5f * sb.y;
        const float2 bb = s_gt[mseg];
        const float qx = bb.x * tk + ax * rt;
        const float qy = bb.y * tk + ay * rt;
        const float2 pv = pp[tid];
        c1 = fabsf(pv.x - qx) + fabsf(pv.y - qy);

        const float2 nearp = pp[(int)bi0];
        const float  mk = kmask[(size_t)b * MPTS + tid];
        c2 = (fabsf(nearp.x - gx) + fabsf(nearp.y - gy)) * mk;
        c3 = 2.0f * mk;
    }

    // ---- reduction: warp shuffles, 4 warp partials ----
    #pragma unroll
    for (int o = 16; o > 0; o >>= 1) {
        c1 += __shfl_down_sync(0xFFFFFFFFu, c1, o);
        c2 += __shfl_down_sync(0xFFFFFFFFu, c2, o);
        c3 += __shfl_down_sync(0xFFFFFFFFu, c3, o);
    }
    const int w = tid >> 5;
    if ((tid & 31) == 0) { s_r1[w] = c1; s_r2[w] = c2; s_r3[w] = c3; }
    __syncthreads();
    if (tid == 0) {
        float a = 0.0f, bsum = 0.0f, cc = 0.0f;
        #pragma unroll
        for (int i = 0; i < 4; i++) { a += s_r1[i]; bsum += s_r2[i]; cc += s_r3[i]; }
        g_part1[b] = a; g_part2[b] = bsum; g_part3[b] = cc;
        __threadfence();
        const unsigned old = atomicAdd(&g_count, 1u);
        s_last = (old == (unsigned)(BATCH - 1)) ? 1 : 0;
    }
    __syncthreads();

    // ---- last block: deterministic final reduction ----
    if (s_last) {
        float a = 0.0f, bsum = 0.0f, cc = 0.0f;
        #pragma unroll
        for (int i = tid; i < BATCH; i += 128) {
            a    += g_part1[i];
            bsum += g_part2[i];
            cc   += g_part3[i];
        }
        #pragma unroll
        for (int o = 16; o > 0; o >>= 1) {
            a    += __shfl_down_sync(0xFFFFFFFFu, a, o);
            bsum += __shfl_down_sync(0xFFFFFFFFu, bsum, o);
            cc   += __shfl_down_sync(0xFFFFFFFFu, cc, o);
        }
        if ((tid & 31) == 0) { s_r1[w] = a; s_r2[w] = bsum; s_r3[w] = cc; }
        __syncthreads();
        if (tid == 0) {
            float fa = 0.0f, fb = 0.0f, fc = 0.0f;
            #pragma unroll
            for (int i = 0; i < 4; i++) { fa += s_r1[i]; fb += s_r2[i]; fc += s_r3[i]; }
            const float loss_pred2gt = fa / (float)(BATCH * NPTS * 2);
            const float loss_gt2pred = fb / (fc + 1.0f);
            out[0] = (loss_gt2pred + loss_pred2gt) * 0.5f;
            g_count = 0;   // reset for next graph replay
        }
    }
}

extern "C" void kernel_launch(void* const* d_in, const int* in_sizes, int n_in,
                              void* d_out, int out_size)
{
    const float* ini_pred   = (const float*)d_in[0];
    const float* pred_polys = (const float*)d_in[1];
    const float* gt_polys   = (const float*)d_in[2];
    const float* kmask      = (const float*)d_in[3];
    float* out = (float*)d_out;

    dmloss_fused<<<BATCH, 128>>>(ini_pred, pred_polys, gt_polys, kmask, out);
}

// round 9
// speedup vs baseline: 1.8517x; 1.1983x over previous
#include <cuda_runtime.h>

#define BATCH 1024
#define NPTS  128
#define MPTS  128
#define TIME  10

#define MAGIC 12582912.0f            /* 1.5 * 2^23 : round-to-nearest-even shifter */
#define KEYMASK 0xFFFFFF80

// Scratch (no allocation allowed) + cross-block completion counter
__device__ float g_part1[BATCH];
__device__ float g_part2[BATCH];
__device__ float g_part3[BATCH];
__device__ unsigned int g_count = 0;

// ---- f32x2 packed helpers (sm_103a) ----
__device__ __forceinline__ unsigned long long pk2(float a, float b) {
    unsigned long long r;
    asm("mov.b64 %0, {%1, %2};" : "=l"(r) : "f"(a), "f"(b));
    return r;
}
__device__ __forceinline__ float2 upk2(unsigned long long v) {
    float2 r;
    asm("mov.b64 {%0, %1}, %2;" : "=f"(r.x), "=f"(r.y) : "l"(v));
    return r;
}
__device__ __forceinline__ unsigned long long fma2_(unsigned long long a, unsigned long long b, unsigned long long c) {
    unsigned long long d;
    asm("fma.rn.f32x2 %0, %1, %2, %3;" : "=l"(d) : "l"(a), "l"(b), "l"(c));
    return d;
}
__device__ __forceinline__ unsigned long long add2_(unsigned long long a, unsigned long long b) {
    unsigned long long d;
    asm("add.rn.f32x2 %0, %1, %2;" : "=l"(d) : "l"(a), "l"(b));
    return d;
}
__device__ __forceinline__ unsigned long long mul2_(unsigned long long a, unsigned long long b) {
    unsigned long long d;
    asm("mul.rn.f32x2 %0, %1, %2;" : "=l"(d) : "l"(a), "l"(b));
    return d;
}
__device__ __forceinline__ void lds_v2(const void* p, unsigned long long& a, unsigned long long& b) {
    unsigned s = (unsigned)__cvta_generic_to_shared(p);
    asm volatile("ld.shared.v2.b64 {%0, %1}, [%2];" : "=l"(a), "=l"(b) : "r"(s));
}
__device__ __forceinline__ unsigned long long lds_b64(const void* p) {
    unsigned s = (unsigned)__cvta_generic_to_shared(p);
    unsigned long long a;
    asm volatile("ld.shared.b64 %0, [%1];" : "=l"(a) : "r"(s));
    return a;
}

__global__ __launch_bounds__(128, 7)
void dmloss_fused(const float* __restrict__ ini_pred,   // [B,N,2]
                  const float* __restrict__ pred_polys, // [B,N,2]
                  const float* __restrict__ gt_polys,   // [B,M,2]
                  const float* __restrict__ kmask,      // [B,M]
                  float* __restrict__ out)
{
    // pair-interleaved layouts: entry j holds fields for candidates 2j (even) and 2j+1 (odd)
    __shared__ float4 sA[MPTS / 2];   // (ex5_e, ex5_o, ey5_e, ey5_o)
    __shared__ float4 sB[MPTS / 2];   // (c_e,   c_o,   e2c_e, e2c_o)
    __shared__ float4 sC[MPTS / 2];   // (ad5_e, ad5_o, a2_e,  a2_o )   ad5 = a.(0.2e), a2=|a|^2
    __shared__ float4 sD[MPTS / 2];   // (m2ax_e,m2ax_o,m2ay_e,m2ay_o)
    __shared__ float4 sP[NPTS / 2];   // (qx_e, qx_o, qy_e, qy_o)       ini_pred
    __shared__ float2 sQ[NPTS / 2];   // (qz_e, qz_o)   qz = 0.5|q|^2
    __shared__ float2 s_gt[MPTS];     // current vertex b (epilogue)
    __shared__ float  s_step[TIME];   // exact k/10 (epilogue only)
    __shared__ float  s_r1[4], s_r2[4], s_r3[4];
    __shared__ int    s_last;

    const int tid = threadIdx.x;
    const int b   = blockIdx.x;
    const int j   = tid >> 1;
    const int e   = tid & 1;

    // ---- setup (each thread: one segment + one pred point, scattered into pair slots) ----
    const float2* gt = (const float2*)(gt_polys + (size_t)b * MPTS * 2);
    const float2 bcur  = gt[tid];
    const float2 aprev = gt[(tid + MPTS - 1) & (MPTS - 1)];
    {
        const float ex  = bcur.x - aprev.x;
        const float ey  = bcur.y - aprev.y;
        const float e2  = ex * ex + ey * ey;
        const float ex5 = 0.2f * ex;
        const float ey5 = 0.2f * ey;
        ((float*)&sA[j])[e]     = ex5;
        ((float*)&sA[j])[2 + e] = ey5;
        ((float*)&sB[j])[e]     = -50.0f / fmaxf(e2, 1e-30f);
        ((float*)&sB[j])[2 + e] = 0.01f * e2;
        ((float*)&sC[j])[e]     = fmaf(aprev.x, ex5, aprev.y * ey5);
        ((float*)&sC[j])[2 + e] = fmaf(aprev.x, aprev.x, aprev.y * aprev.y);
        ((float*)&sD[j])[e]     = -2.0f * aprev.x;
        ((float*)&sD[j])[2 + e] = -2.0f * aprev.y;
        s_gt[tid] = bcur;
    }
    const float2* ip = (const float2*)(ini_pred + (size_t)b * NPTS * 2);
    const float2 p = ip[tid];
    ((float*)&sP[j])[e]     = p.x;
    ((float*)&sP[j])[2 + e] = p.y;
    ((float*)&sQ[j])[e]     = 0.5f * fmaf(p.x, p.x, p.y * p.y);
    if (tid < TIME) s_step[tid] = (float)tid / 10.0f;
    __syncthreads();

    const float px = p.x, py = p.y;
    const float gx = bcur.x, gy = bcur.y;
    const float p2 = fmaf(px, px, py * py);
    const float hg = 0.5f * fmaf(gx, gx, gy * gy);

    // packed thread constants
    const unsigned long long px2  = pk2(px, px);
    const unsigned long long py2  = pk2(py, py);
    const unsigned long long npx2 = pk2(-px, -px);
    const unsigned long long npy2 = pk2(-py, -py);
    const unsigned long long p22  = pk2(p2, p2);
    const unsigned long long ngx2 = pk2(-gx, -gx);
    const unsigned long long ngy2 = pk2(-gy, -gy);
    const unsigned long long hg2  = pk2(hg, hg);
    const unsigned long long M2   = pk2(MAGIC, MAGIC);
    const unsigned long long NM2  = pk2(-MAGIC, -MAGIC);
    const int LOB = __float_as_int(MAGIC);          // bits of MAGIC + 0
    const int HIB = __float_as_int(MAGIC + 9.0f);   // bits of MAGIC + 9

    int key1 = 0x7FFFFFFF;   // (dist2 bits & ~0x7F) | segment index
    int key2 = 0x7FFFFFFF;   // (dist2 bits & ~0x7F) | pred index
    int nE = 0, nO = 1;

    #pragma unroll 4
    for (int i = 0; i < 64; i++) {
        // ---- segment pair (2i, 2i+1): pred -> interp-gt ----
        {
            unsigned long long ex2, ey2, c2v, ec2, ad2, a22, mx2, my2;
            lds_v2(&sA[i], ex2, ey2);
            lds_v2(&sB[i], c2v, ec2);
            lds_v2(&sC[i], ad2, a22);
            lds_v2(&sD[i], mx2, my2);
            const unsigned long long wd2 = fma2_(npx2, ex2, fma2_(npy2, ey2, ad2)); // 0.2 w.e
            const unsigned long long kf2 = mul2_(wd2, c2v);                          // minimizer k
            const unsigned long long t2  = add2_(kf2, M2);
            const float2 tf = upk2(t2);
            const int tiA = min(max(__float_as_int(tf.x), LOB), HIB);                // clamp k to [0,9]
            const int tiB = min(max(__float_as_int(tf.y), LOB), HIB);
            const unsigned long long kr2 = add2_(pk2(__int_as_float(tiA), __int_as_float(tiB)), NM2);
            const unsigned long long a2p  = add2_(a22, p22);
            const unsigned long long base = fma2_(px2, mx2, fma2_(py2, my2, a2p));   // |a-p|^2
            const unsigned long long sc2  = fma2_(kr2, fma2_(kr2, ec2, wd2), base);  // dist^2 at sample
            const float2 sf = upk2(sc2);
            const int kA = (__float_as_int(sf.x) & KEYMASK) | nE;
            const int kB = (__float_as_int(sf.y) & KEYMASK) | nO;
            key1 = min(key1, kA);
            key1 = min(key1, kB);
        }
        // ---- pred pair (2i, 2i+1): gt -> pred ----
        {
            unsigned long long qx2, qy2;
            lds_v2(&sP[i], qx2, qy2);
            const unsigned long long qz2 = lds_b64(&sQ[i]);
            const unsigned long long s2 = add2_(qz2, fma2_(ngx2, qx2, fma2_(ngy2, qy2, hg2))); // 0.5|q-g|^2
            const float2 pf = upk2(s2);
            const int jA = (__float_as_int(pf.x) & KEYMASK) | nE;
            const int jB = (__float_as_int(pf.y) & KEYMASK) | nO;
            key2 = min(key2, jA);
            key2 = min(key2, jB);
        }
        nE += 2; nO += 2;
    }

    // ---- epilogue: recover winners, compute contributions (reference-form interp) ----
    const float2* pp = (const float2*)(pred_polys + (size_t)b * NPTS * 2);
    float c1, c2, c3;
    {
        const int mh = key1 & 0x7F;
        const int jj = mh >> 1, ee = mh & 1;
        const float ex5  = ((float*)&sA[jj])[ee];
        const float ey5  = ((float*)&sA[jj])[2 + ee];
        const float cm   = ((float*)&sB[jj])[ee];
        const float ad5  = ((float*)&sC[jj])[ee];
        const float m2ax = ((float*)&sD[jj])[ee];
        const float m2ay = ((float*)&sD[jj])[2 + ee];
        // bit-identical recompute of kr for winning segment
        const float wd2 = fmaf(-px, ex5, fmaf(-py, ey5, ad5));
        const float kf  = wd2 * cm;
        const float t   = __fadd_rn(kf, MAGIC);
        const int   ti  = min(max(__float_as_int(t), LOB), HIB);
        const float kr  = __fadd_rn(__int_as_float(ti), -MAGIC);
        const int   k   = (int)kr;
        const float tk  = s_step[k];
        const float rt  = 1.0f - tk;
        const float ax  = -0.5f * m2ax;      // exact recovery of aprev
        const float ay  = -0.5f * m2ay;
        const float2 bb = s_gt[mh];
        const float qx = bb.x * tk + ax * rt;
        const float qy = bb.y * tk + ay * rt;
        const float2 pv = pp[tid];
        c1 = fabsf(pv.x - qx) + fabsf(pv.y - qy);

        const float2 nearp = pp[key2 & 0x7F];
        const float  mk = kmask[(size_t)b * MPTS + tid];
        c2 = (fabsf(nearp.x - gx) + fabsf(nearp.y - gy)) * mk;
        c3 = 2.0f * mk;
    }

    // ---- reduction: warp shuffles, 4 warp partials ----
    #pragma unroll
    for (int o = 16; o > 0; o >>= 1) {
        c1 += __shfl_down_sync(0xFFFFFFFFu, c1, o);
        c2 += __shfl_down_sync(0xFFFFFFFFu, c2, o);
        c3 += __shfl_down_sync(0xFFFFFFFFu, c3, o);
    }
    const int w = tid >> 5;
    if ((tid & 31) == 0) { s_r1[w] = c1; s_r2[w] = c2; s_r3[w] = c3; }
    __syncthreads();
    if (tid == 0) {
        float a = 0.0f, bsum = 0.0f, cc = 0.0f;
        #pragma unroll
        for (int i = 0; i < 4; i++) { a += s_r1[i]; bsum += s_r2[i]; cc += s_r3[i]; }
        g_part1[b] = a; g_part2[b] = bsum; g_part3[b] = cc;
        __threadfence();
        const unsigned old = atomicAdd(&g_count, 1u);
        s_last = (old == (unsigned)(BATCH - 1)) ? 1 : 0;
    }
    __syncthreads();

    // ---- last block: deterministic final reduction ----
    if (s_last) {
        float a = 0.0f, bsum = 0.0f, cc = 0.0f;
        #pragma unroll
        for (int i = tid; i < BATCH; i += 128) {
            a    += g_part1[i];
            bsum += g_part2[i];
            cc   += g_part3[i];
        }
        #pragma unroll
        for (int o = 16; o > 0; o >>= 1) {
            a    += __shfl_down_sync(0xFFFFFFFFu, a, o);
            bsum += __shfl_down_sync(0xFFFFFFFFu, bsum, o);
            cc   += __shfl_down_sync(0xFFFFFFFFu, cc, o);
        }
        if ((tid & 31) == 0) { s_r1[w] = a; s_r2[w] = bsum; s_r3[w] = cc; }
        __syncthreads();
        if (tid == 0) {
            float fa = 0.0f, fb = 0.0f, fc = 0.0f;
            #pragma unroll
            for (int i = 0; i < 4; i++) { fa += s_r1[i]; fb += s_r2[i]; fc += s_r3[i]; }
            const float loss_pred2gt = fa / (float)(BATCH * NPTS * 2);
            const float loss_gt2pred = fb / (fc + 1.0f);
            out[0] = (loss_gt2pred + loss_pred2gt) * 0.5f;
            g_count = 0;   // reset for next graph replay
        }
    }
}

extern "C" void kernel_launch(void* const* d_in, const int* in_sizes, int n_in,
                              void* d_out, int out_size)
{
    const float* ini_pred   = (const float*)d_in[0];
    const float* pred_polys = (const float*)d_in[1];
    const float* gt_polys   = (const float*)d_in[2];
    const float* kmask      = (const float*)d_in[3];
    float* out = (float*)d_out;

    dmloss_fused<<<BATCH, 128>>>(ini_pred, pred_polys, gt_polys, kmask, out);
}